// round 14
// baseline (speedup 1.0000x reference)
#include <cuda_runtime.h>
#include <cuda_fp16.h>
#include <math.h>
#include <stdint.h>

// Shape (fixed): B=8, S=2048, D=1024, U=1024, A=4
#define M_TOT 16384
#define N_TOT 1024
#define K_TOT 1024

// GEMM tiling: fp16 mma.sync, 128 threads/CTA, CTA tile 128x128,
// warp tile 64x64 (2x2 warps), NSTAGE=5 deep pipeline, 2 CTAs/SM
#define BM 128
#define BN 128
#define BKC 32            // fp16 K elems per stage chunk
#define NSTAGE 5
#define NITER 32          // 1024/32

// SMEM stage layout: padded rows for conflict-free ldmatrix
#define LDA 40            // A row stride in fp16 elems (80 B)
#define LDB 136           // B row stride in fp16 elems (272 B)
#define STAGE_A_BYTES (BM * LDA * 2)      // 10240
#define STAGE_B_BYTES (BKC * LDB * 2)     // 8704
#define STAGE_BYTES   (STAGE_A_BYTES + STAGE_B_BYTES)   // 18944
#define SM_ATTN  0                         // 128 * float4 = 2048
#define SM_B     2048                      // 128 * float  = 512
#define SM_WF    2560                      // 128 * float4 = 2048
#define SM_BF    4608                      // 128 * float4 = 2048
#define SM_STAGE 6656
#define SM_TOTAL (SM_STAGE + NSTAGE * STAGE_BYTES)      // 101376 (2 CTAs/SM)

// ---------------- scratch (device globals; no allocation allowed) ----------
__device__ __half g_xh[(size_t)M_TOT * K_TOT];
__device__ __half g_wh[(size_t)K_TOT * N_TOT];   // w fp16, [K][N]
__device__ float g_attn[(size_t)M_TOT * 4];

// ---------------- helpers ---------------------------------------------------
__device__ __forceinline__ uint32_t smem_u32(const void* p) {
    return (uint32_t)__cvta_generic_to_shared(p);
}
__device__ __forceinline__ void cp16(uint32_t s, const void* g) {
    asm volatile("cp.async.cg.shared.global [%0], [%1], 16;" :: "r"(s), "l"(g));
}
__device__ __forceinline__ void cp_commit() {
    asm volatile("cp.async.commit_group;" ::: "memory");
}
__device__ __forceinline__ void cp_wait3() {
    asm volatile("cp.async.wait_group 3;" ::: "memory");
}
__device__ __forceinline__ void ldsm_x4(uint32_t* r, uint32_t a) {
    asm volatile("ldmatrix.sync.aligned.m8n8.x4.shared.b16 {%0,%1,%2,%3}, [%4];"
                 : "=r"(r[0]), "=r"(r[1]), "=r"(r[2]), "=r"(r[3]) : "r"(a));
}
__device__ __forceinline__ void ldsm_x4_t(uint32_t* r, uint32_t a) {
    asm volatile("ldmatrix.sync.aligned.m8n8.x4.trans.shared.b16 {%0,%1,%2,%3}, [%4];"
                 : "=r"(r[0]), "=r"(r[1]), "=r"(r[2]), "=r"(r[3]) : "r"(a));
}
__device__ __forceinline__ void mma_fp16(float* c, const uint32_t* a,
                                         uint32_t b0, uint32_t b1) {
    asm volatile(
        "mma.sync.aligned.m16n8k16.row.col.f32.f16.f16.f32 "
        "{%0,%1,%2,%3}, {%4,%5,%6,%7}, {%8,%9}, {%0,%1,%2,%3};"
        : "+f"(c[0]), "+f"(c[1]), "+f"(c[2]), "+f"(c[3])
        : "r"(a[0]), "r"(a[1]), "r"(a[2]), "r"(a[3]), "r"(b0), "r"(b1));
}

// ---------------------------------------------------------------------------
// Prep (merged): blocks [0, 512): attention softmax + x->fp16 (4 rows/warp,
// w_att fragment amortized). Blocks [512, 768): w -> fp16 elementwise.
// ---------------------------------------------------------------------------
__global__ __launch_bounds__(256) void prep_all(const float* __restrict__ x,
                                                const float* __restrict__ w,
                                                const float* __restrict__ w_att,
                                                const float* __restrict__ b_att) {
    if (blockIdx.x >= 512) {
        int base = (blockIdx.x - 512) * 1024 + threadIdx.x;
#pragma unroll
        for (int j = 0; j < 4; j++) {
            int i = base + j * 256;
            float4 v = ((const float4*)w)[i];
            unsigned short h0 = __half_as_ushort(__float2half_rn(v.x));
            unsigned short h1 = __half_as_ushort(__float2half_rn(v.y));
            unsigned short h2 = __half_as_ushort(__float2half_rn(v.z));
            unsigned short h3 = __half_as_ushort(__float2half_rn(v.w));
            ((uint2*)g_wh)[i] = make_uint2((uint32_t)h0 | ((uint32_t)h1 << 16),
                                           (uint32_t)h2 | ((uint32_t)h3 << 16));
        }
        return;
    }

    int warp = threadIdx.x >> 5;
    int lane = threadIdx.x & 31;
    int row0 = (blockIdx.x * 8 + warp) * 4;
    const float4* x4  = (const float4*)x;
    const float4* wa4 = (const float4*)w_att;

    float acc[4][4];
#pragma unroll
    for (int r = 0; r < 4; r++)
#pragma unroll
        for (int j = 0; j < 4; j++) acc[r][j] = 0.f;

#pragma unroll
    for (int i = 0; i < 8; i++) {
        int q = i * 32 + lane;
        float4 w0 = wa4[q * 4 + 0], w1 = wa4[q * 4 + 1];
        float4 w2 = wa4[q * 4 + 2], w3 = wa4[q * 4 + 3];
#pragma unroll
        for (int r = 0; r < 4; r++) {
            float4 v = x4[(size_t)(row0 + r) * 256 + q];
            acc[r][0] = fmaf(v.x, w0.x, fmaf(v.y, w1.x,
                        fmaf(v.z, w2.x, fmaf(v.w, w3.x, acc[r][0]))));
            acc[r][1] = fmaf(v.x, w0.y, fmaf(v.y, w1.y,
                        fmaf(v.z, w2.y, fmaf(v.w, w3.y, acc[r][1]))));
            acc[r][2] = fmaf(v.x, w0.z, fmaf(v.y, w1.z,
                        fmaf(v.z, w2.z, fmaf(v.w, w3.z, acc[r][2]))));
            acc[r][3] = fmaf(v.x, w0.w, fmaf(v.y, w1.w,
                        fmaf(v.z, w2.w, fmaf(v.w, w3.w, acc[r][3]))));
            unsigned short h0 = __half_as_ushort(__float2half_rn(v.x));
            unsigned short h1 = __half_as_ushort(__float2half_rn(v.y));
            unsigned short h2 = __half_as_ushort(__float2half_rn(v.z));
            unsigned short h3 = __half_as_ushort(__float2half_rn(v.w));
            ((uint2*)g_xh)[(size_t)(row0 + r) * 256 + q] =
                make_uint2((uint32_t)h0 | ((uint32_t)h1 << 16),
                           (uint32_t)h2 | ((uint32_t)h3 << 16));
        }
    }
#pragma unroll
    for (int r = 0; r < 4; r++)
#pragma unroll
        for (int off = 16; off; off >>= 1) {
            acc[r][0] += __shfl_xor_sync(0xffffffffu, acc[r][0], off);
            acc[r][1] += __shfl_xor_sync(0xffffffffu, acc[r][1], off);
            acc[r][2] += __shfl_xor_sync(0xffffffffu, acc[r][2], off);
            acc[r][3] += __shfl_xor_sync(0xffffffffu, acc[r][3], off);
        }
    if (lane < 4) {
        float a0 = acc[lane][0] + b_att[0];
        float a1 = acc[lane][1] + b_att[1];
        float a2 = acc[lane][2] + b_att[2];
        float a3 = acc[lane][3] + b_att[3];
        float mx = fmaxf(fmaxf(a0, a1), fmaxf(a2, a3));
        float e0 = expf(a0 - mx), e1 = expf(a1 - mx);
        float e2 = expf(a2 - mx), e3 = expf(a3 - mx);
        float inv = 1.f / (e0 + e1 + e2 + e3);
        ((float4*)g_attn)[row0 + lane] =
            make_float4(e0 * inv, e1 * inv, e2 * inv, e3 * inv);
    }
}

// ---------------------------------------------------------------------------
// Main fused GEMM: fp16 mma.sync, warp tile 64x64, 5-stage pipeline
// (wait_group 3 => ~3 chunks of cp.async lead time). 128 threads, 2 CTAs/SM.
// ---------------------------------------------------------------------------
__device__ __forceinline__ void issue_stage(char* smem, int idx, int t,
                                            int bm, int bn) {
    int kt = idx * BKC;
    char* A = smem + SM_STAGE + (idx % NSTAGE) * STAGE_BYTES;
    char* B = A + STAGE_A_BYTES;
#pragma unroll
    for (int i = 0; i < 4; i++) {
        int id  = t + i * 128;
        int row = id >> 2, cq = id & 3;
        cp16(smem_u32(A + row * (LDA * 2) + cq * 16),
             g_xh + (size_t)(bm + row) * K_TOT + kt + cq * 8);
    }
#pragma unroll
    for (int i = 0; i < 4; i++) {
        int id  = t + i * 128;
        int row = id >> 4, cq = id & 15;
        cp16(smem_u32(B + row * (LDB * 2) + cq * 16),
             g_wh + (size_t)(kt + row) * N_TOT + bn + cq * 8);
    }
    cp_commit();
}

__global__ __launch_bounds__(128, 2)
void fused_gemm_hmma(const float* __restrict__ b,
                     const float* __restrict__ wf,
                     const float* __restrict__ bf,
                     float* __restrict__ out) {
    extern __shared__ char smem[];
    const int t    = threadIdx.x;
    const int wid  = t >> 5;
    const int lane = t & 31;
    const int bm   = blockIdx.y * BM;
    const int bn   = blockIdx.x * BN;
    const int m0   = (wid >> 1) * 64;    // warp M offset
    const int n0   = (wid & 1) * 64;     // warp N offset

    // Stage epilogue tables (128 threads)
    ((float4*)(smem + SM_ATTN))[t] = ((const float4*)g_attn)[bm + t];
    ((float*)(smem + SM_B))[t]     = b[bn + t];
    ((float4*)(smem + SM_WF))[t]   = ((const float4*)wf)[bn + t];
    ((float4*)(smem + SM_BF))[t]   = ((const float4*)bf)[bn + t];

    issue_stage(smem, 0, t, bm, bn);
    issue_stage(smem, 1, t, bm, bn);
    issue_stage(smem, 2, t, bm, bn);
    issue_stage(smem, 3, t, bm, bn);

    float c[4][8][4];
#pragma unroll
    for (int mt = 0; mt < 4; mt++)
#pragma unroll
        for (int nt = 0; nt < 8; nt++)
#pragma unroll
            for (int r = 0; r < 4; r++) c[mt][nt][r] = 0.f;

    const int lrow = lane & 15;
    const int lcol = (lane >> 4) * 8;

    // Fragment double buffers
    uint32_t af[2][4][4], bb[2][4][4];

#define LDFRAG(buf, Aptr, Bptr, k0)                                           \
    do {                                                                      \
        _Pragma("unroll")                                                     \
        for (int mt = 0; mt < 4; mt++)                                        \
            ldsm_x4(af[buf][mt], smem_u32((Aptr) +                            \
                    ((m0 + mt * 16 + lrow) * LDA + (k0) + lcol) * 2));        \
        _Pragma("unroll")                                                     \
        for (int ng = 0; ng < 4; ng++)                                        \
            ldsm_x4_t(bb[buf][ng], smem_u32((Bptr) +                          \
                    (((k0) + lrow) * LDB + n0 + ng * 16 + lcol) * 2));        \
    } while (0)

#define MMA_ALL(buf)                                                          \
    do {                                                                      \
        _Pragma("unroll")                                                     \
        for (int mt = 0; mt < 4; mt++)                                        \
            _Pragma("unroll")                                                 \
            for (int nt = 0; nt < 8; nt++)                                    \
                mma_fp16(c[mt][nt], af[buf][mt],                              \
                         bb[buf][nt >> 1][(nt & 1) * 2],                      \
                         bb[buf][nt >> 1][(nt & 1) * 2 + 1]);                 \
    } while (0)

    cp_wait3();        // stage 0 complete (3 newer groups may be in flight)
    __syncthreads();
    {
        char* A0 = smem + SM_STAGE;
        LDFRAG(0, A0, A0 + STAGE_A_BYTES, 0);   // chunk 0, k-group 0
    }

    for (int i = 0; i < NITER; i++) {
        char* A = smem + SM_STAGE + (i % NSTAGE) * STAGE_BYTES;
        char* B = A + STAGE_A_BYTES;

        LDFRAG(1, A, B, 16);                    // kg1 of chunk i
        if (i + 4 < NITER) issue_stage(smem, i + 4, t, bm, bn);
        MMA_ALL(0);                             // kg0
        cp_wait3();
        __syncthreads();   // stage i+1 ready; all reads of slot (i+4)%5 done

        if (i + 1 < NITER) {
            char* An = smem + SM_STAGE + ((i + 1) % NSTAGE) * STAGE_BYTES;
            LDFRAG(0, An, An + STAGE_A_BYTES, 0);   // next chunk kg0
        }
        MMA_ALL(1);                             // kg1
    }

    // Epilogue: bias -> per-activation affine -> activations -> attn mix
    const float*  sB  = (const float*)(smem + SM_B);
    const float4* sWF = (const float4*)(smem + SM_WF);
    const float4* sBF = (const float4*)(smem + SM_BF);
    const float4* sAT = (const float4*)(smem + SM_ATTN);
    const float inv_sqrt2 = 0.70710678118654752f;

#pragma unroll
    for (int mt = 0; mt < 4; mt++) {
#pragma unroll
        for (int half = 0; half < 2; half++) {
            int lr = m0 + mt * 16 + (lane >> 2) + half * 8;
            float4 at = sAT[lr];
            float* orow = out + (size_t)(bm + lr) * N_TOT + bn;
#pragma unroll
            for (int nt = 0; nt < 8; nt++) {
                int col0 = n0 + nt * 8 + (lane & 3) * 2;
                float2 res;
#pragma unroll
                for (int h = 0; h < 2; h++) {
                    int col = col0 + h;
                    float s = c[mt][nt][half * 2 + h] + sB[col];
                    float4 wfv = sWF[col];
                    float4 bfv = sBF[col];
                    float z0 = fmaf(s, wfv.x, bfv.x);
                    float z1 = fmaf(s, wfv.y, bfv.y);
                    float z2 = fmaf(s, wfv.z, bfv.z);
                    float z3 = fmaf(s, wfv.w, bfv.w);
                    float r0 = fmaxf(z0, 0.f);
                    float r1 = __fdividef(1.f, 1.f + __expf(-z1));
                    float r2 = 1.f - __fdividef(2.f, __expf(2.f * z2) + 1.f);
                    float r3 = 0.5f * z3 * (1.f + erff(z3 * inv_sqrt2));
                    float v = r0 * at.x + r1 * at.y + r2 * at.z + r3 * at.w;
                    if (h == 0) res.x = v; else res.y = v;
                }
                *(float2*)(orow + col0) = res;
            }
        }
    }
}

// ---------------------------------------------------------------------------
extern "C" void kernel_launch(void* const* d_in, const int* in_sizes, int n_in,
                              void* d_out, int out_size) {
    const float* x     = (const float*)d_in[0];
    const float* w     = (const float*)d_in[1];
    const float* b     = (const float*)d_in[2];
    const float* wf    = (const float*)d_in[3];
    const float* bf    = (const float*)d_in[4];
    const float* w_att = (const float*)d_in[5];
    const float* b_att = (const float*)d_in[6];
    float* out = (float*)d_out;

    cudaFuncSetAttribute(fused_gemm_hmma,
                         cudaFuncAttributeMaxDynamicSharedMemorySize, SM_TOTAL);

    prep_all<<<768, 256>>>(x, w, w_att, b_att);
    fused_gemm_hmma<<<dim3(N_TOT / BN, M_TOT / BM), 128, SM_TOTAL>>>(b, wf, bf, out);
}

// round 15
// speedup vs baseline: 1.1699x; 1.1699x over previous
#include <cuda_runtime.h>
#include <cuda_fp16.h>
#include <math.h>
#include <stdint.h>

// Shape (fixed): B=8, S=2048, D=1024, U=1024, A=4
#define M_TOT 16384
#define N_TOT 1024
#define K_TOT 1024

// GEMM tiling: fp16 mma.sync, 128 threads/CTA, CTA tile 128x64,
// warp tile 64x32 (2x2 warps), NSTAGE=4, 3 CTAs/SM (tail-quantization fix)
#define BM 128
#define BN 64
#define BKC 32            // fp16 K elems per stage chunk
#define NSTAGE 4
#define NITER 32          // 1024/32

// SMEM stage layout: padded rows for conflict-free ldmatrix
#define LDA 40            // A row stride in fp16 elems (80 B)
#define LDB 72            // B row stride in fp16 elems (144 B; 144%128=16)
#define STAGE_A_BYTES (BM * LDA * 2)      // 10240
#define STAGE_B_BYTES (BKC * LDB * 2)     // 4608
#define STAGE_BYTES   (STAGE_A_BYTES + STAGE_B_BYTES)   // 14848
#define SM_ATTN  0                         // 128 * float4 = 2048
#define SM_B     2048                      // 64 * float   = 256
#define SM_WF    2304                      // 64 * float4  = 1024
#define SM_BF    3328                      // 64 * float4  = 1024
#define SM_STAGE 4352
#define SM_TOTAL (SM_STAGE + NSTAGE * STAGE_BYTES)      // 63744 (3 CTAs/SM)

// ---------------- scratch (device globals; no allocation allowed) ----------
__device__ __half g_xh[(size_t)M_TOT * K_TOT];
__device__ __half g_wh[(size_t)K_TOT * N_TOT];   // w fp16, [K][N]
__device__ float g_attn[(size_t)M_TOT * 4];

// ---------------- helpers ---------------------------------------------------
__device__ __forceinline__ uint32_t smem_u32(const void* p) {
    return (uint32_t)__cvta_generic_to_shared(p);
}
__device__ __forceinline__ void cp16(uint32_t s, const void* g) {
    asm volatile("cp.async.cg.shared.global [%0], [%1], 16;" :: "r"(s), "l"(g));
}
__device__ __forceinline__ void cp_commit() {
    asm volatile("cp.async.commit_group;" ::: "memory");
}
__device__ __forceinline__ void cp_wait2() {
    asm volatile("cp.async.wait_group 2;" ::: "memory");
}
__device__ __forceinline__ void ldsm_x4(uint32_t* r, uint32_t a) {
    asm volatile("ldmatrix.sync.aligned.m8n8.x4.shared.b16 {%0,%1,%2,%3}, [%4];"
                 : "=r"(r[0]), "=r"(r[1]), "=r"(r[2]), "=r"(r[3]) : "r"(a));
}
__device__ __forceinline__ void ldsm_x4_t(uint32_t* r, uint32_t a) {
    asm volatile("ldmatrix.sync.aligned.m8n8.x4.trans.shared.b16 {%0,%1,%2,%3}, [%4];"
                 : "=r"(r[0]), "=r"(r[1]), "=r"(r[2]), "=r"(r[3]) : "r"(a));
}
__device__ __forceinline__ void mma_fp16(float* c, const uint32_t* a,
                                         uint32_t b0, uint32_t b1) {
    asm volatile(
        "mma.sync.aligned.m16n8k16.row.col.f32.f16.f16.f32 "
        "{%0,%1,%2,%3}, {%4,%5,%6,%7}, {%8,%9}, {%0,%1,%2,%3};"
        : "+f"(c[0]), "+f"(c[1]), "+f"(c[2]), "+f"(c[3])
        : "r"(a[0]), "r"(a[1]), "r"(a[2]), "r"(a[3]), "r"(b0), "r"(b1));
}

// ---------------------------------------------------------------------------
// Prep (merged): blocks [0, 512): attention softmax + x->fp16 (4 rows/warp,
// w_att fragment amortized). Blocks [512, 768): w -> fp16 elementwise.
// ---------------------------------------------------------------------------
__global__ __launch_bounds__(256) void prep_all(const float* __restrict__ x,
                                                const float* __restrict__ w,
                                                const float* __restrict__ w_att,
                                                const float* __restrict__ b_att) {
    if (blockIdx.x >= 512) {
        int base = (blockIdx.x - 512) * 1024 + threadIdx.x;
#pragma unroll
        for (int j = 0; j < 4; j++) {
            int i = base + j * 256;
            float4 v = ((const float4*)w)[i];
            unsigned short h0 = __half_as_ushort(__float2half_rn(v.x));
            unsigned short h1 = __half_as_ushort(__float2half_rn(v.y));
            unsigned short h2 = __half_as_ushort(__float2half_rn(v.z));
            unsigned short h3 = __half_as_ushort(__float2half_rn(v.w));
            ((uint2*)g_wh)[i] = make_uint2((uint32_t)h0 | ((uint32_t)h1 << 16),
                                           (uint32_t)h2 | ((uint32_t)h3 << 16));
        }
        return;
    }

    int warp = threadIdx.x >> 5;
    int lane = threadIdx.x & 31;
    int row0 = (blockIdx.x * 8 + warp) * 4;
    const float4* x4  = (const float4*)x;
    const float4* wa4 = (const float4*)w_att;

    float acc[4][4];
#pragma unroll
    for (int r = 0; r < 4; r++)
#pragma unroll
        for (int j = 0; j < 4; j++) acc[r][j] = 0.f;

#pragma unroll
    for (int i = 0; i < 8; i++) {
        int q = i * 32 + lane;
        float4 w0 = wa4[q * 4 + 0], w1 = wa4[q * 4 + 1];
        float4 w2 = wa4[q * 4 + 2], w3 = wa4[q * 4 + 3];
#pragma unroll
        for (int r = 0; r < 4; r++) {
            float4 v = x4[(size_t)(row0 + r) * 256 + q];
            acc[r][0] = fmaf(v.x, w0.x, fmaf(v.y, w1.x,
                        fmaf(v.z, w2.x, fmaf(v.w, w3.x, acc[r][0]))));
            acc[r][1] = fmaf(v.x, w0.y, fmaf(v.y, w1.y,
                        fmaf(v.z, w2.y, fmaf(v.w, w3.y, acc[r][1]))));
            acc[r][2] = fmaf(v.x, w0.z, fmaf(v.y, w1.z,
                        fmaf(v.z, w2.z, fmaf(v.w, w3.z, acc[r][2]))));
            acc[r][3] = fmaf(v.x, w0.w, fmaf(v.y, w1.w,
                        fmaf(v.z, w2.w, fmaf(v.w, w3.w, acc[r][3]))));
            unsigned short h0 = __half_as_ushort(__float2half_rn(v.x));
            unsigned short h1 = __half_as_ushort(__float2half_rn(v.y));
            unsigned short h2 = __half_as_ushort(__float2half_rn(v.z));
            unsigned short h3 = __half_as_ushort(__float2half_rn(v.w));
            ((uint2*)g_xh)[(size_t)(row0 + r) * 256 + q] =
                make_uint2((uint32_t)h0 | ((uint32_t)h1 << 16),
                           (uint32_t)h2 | ((uint32_t)h3 << 16));
        }
    }
#pragma unroll
    for (int r = 0; r < 4; r++)
#pragma unroll
        for (int off = 16; off; off >>= 1) {
            acc[r][0] += __shfl_xor_sync(0xffffffffu, acc[r][0], off);
            acc[r][1] += __shfl_xor_sync(0xffffffffu, acc[r][1], off);
            acc[r][2] += __shfl_xor_sync(0xffffffffu, acc[r][2], off);
            acc[r][3] += __shfl_xor_sync(0xffffffffu, acc[r][3], off);
        }
    if (lane < 4) {
        float a0 = acc[lane][0] + b_att[0];
        float a1 = acc[lane][1] + b_att[1];
        float a2 = acc[lane][2] + b_att[2];
        float a3 = acc[lane][3] + b_att[3];
        float mx = fmaxf(fmaxf(a0, a1), fmaxf(a2, a3));
        float e0 = expf(a0 - mx), e1 = expf(a1 - mx);
        float e2 = expf(a2 - mx), e3 = expf(a3 - mx);
        float inv = 1.f / (e0 + e1 + e2 + e3);
        ((float4*)g_attn)[row0 + lane] =
            make_float4(e0 * inv, e1 * inv, e2 * inv, e3 * inv);
    }
}

// ---------------------------------------------------------------------------
// Main fused GEMM: fp16 mma.sync, warp tile 64x32, R9 mainloop schedule.
// 128 threads, 4 warps (2x2), 3 CTAs/SM.
// ---------------------------------------------------------------------------
__device__ __forceinline__ void issue_stage(char* smem, int idx, int t,
                                            int bm, int bn) {
    int kt = idx * BKC;
    char* A = smem + SM_STAGE + (idx % NSTAGE) * STAGE_BYTES;
    char* B = A + STAGE_A_BYTES;
    // A: 128 rows x 4 chunks(16B) = 512 chunks, 4 per thread
#pragma unroll
    for (int i = 0; i < 4; i++) {
        int id  = t + i * 128;
        int row = id >> 2, cq = id & 3;
        cp16(smem_u32(A + row * (LDA * 2) + cq * 16),
             g_xh + (size_t)(bm + row) * K_TOT + kt + cq * 8);
    }
    // B: 32 rows x 8 chunks = 256 chunks, 2 per thread
#pragma unroll
    for (int i = 0; i < 2; i++) {
        int id  = t + i * 128;
        int row = id >> 3, cq = id & 7;
        cp16(smem_u32(B + row * (LDB * 2) + cq * 16),
             g_wh + (size_t)(kt + row) * N_TOT + bn + cq * 8);
    }
    cp_commit();
}

__global__ __launch_bounds__(128, 3)
void fused_gemm_hmma(const float* __restrict__ b,
                     const float* __restrict__ wf,
                     const float* __restrict__ bf,
                     float* __restrict__ out) {
    extern __shared__ char smem[];
    const int t    = threadIdx.x;
    const int wid  = t >> 5;
    const int lane = t & 31;
    const int bm   = blockIdx.y * BM;
    const int bn   = blockIdx.x * BN;
    const int m0   = (wid >> 1) * 64;    // warp M offset
    const int n0   = (wid & 1) * 32;     // warp N offset

    // Stage epilogue tables (128 threads)
    ((float4*)(smem + SM_ATTN))[t] = ((const float4*)g_attn)[bm + t];
    if (t < 64) {
        ((float*)(smem + SM_B))[t]   = b[bn + t];
        ((float4*)(smem + SM_WF))[t] = ((const float4*)wf)[bn + t];
        ((float4*)(smem + SM_BF))[t] = ((const float4*)bf)[bn + t];
    }

    issue_stage(smem, 0, t, bm, bn);
    issue_stage(smem, 1, t, bm, bn);
    issue_stage(smem, 2, t, bm, bn);

    float c[4][4][4];
#pragma unroll
    for (int mt = 0; mt < 4; mt++)
#pragma unroll
        for (int nt = 0; nt < 4; nt++)
#pragma unroll
            for (int r = 0; r < 4; r++) c[mt][nt][r] = 0.f;

    const int lrow = lane & 15;
    const int lcol = (lane >> 4) * 8;

    // Fragment double buffers
    uint32_t af[2][4][4], bb[2][2][4];

#define LDFRAG(buf, Aptr, Bptr, k0)                                           \
    do {                                                                      \
        _Pragma("unroll")                                                     \
        for (int mt = 0; mt < 4; mt++)                                        \
            ldsm_x4(af[buf][mt], smem_u32((Aptr) +                            \
                    ((m0 + mt * 16 + lrow) * LDA + (k0) + lcol) * 2));        \
        _Pragma("unroll")                                                     \
        for (int ng = 0; ng < 2; ng++)                                        \
            ldsm_x4_t(bb[buf][ng], smem_u32((Bptr) +                          \
                    (((k0) + lrow) * LDB + n0 + ng * 16 + lcol) * 2));        \
    } while (0)

#define MMA_ALL(buf)                                                          \
    do {                                                                      \
        _Pragma("unroll")                                                     \
        for (int mt = 0; mt < 4; mt++)                                        \
            _Pragma("unroll")                                                 \
            for (int nt = 0; nt < 4; nt++)                                    \
                mma_fp16(c[mt][nt], af[buf][mt],                              \
                         bb[buf][nt >> 1][(nt & 1) * 2],                      \
                         bb[buf][nt >> 1][(nt & 1) * 2 + 1]);                 \
    } while (0)

    cp_wait2();        // stage 0 complete
    __syncthreads();
    {
        char* A0 = smem + SM_STAGE;
        LDFRAG(0, A0, A0 + STAGE_A_BYTES, 0);   // chunk 0, k-group 0
    }

    for (int i = 0; i < NITER; i++) {
        char* A = smem + SM_STAGE + (i % NSTAGE) * STAGE_BYTES;
        char* B = A + STAGE_A_BYTES;

        LDFRAG(1, A, B, 16);                    // kg1 of chunk i
        MMA_ALL(0);                             // kg0
        if (i + 3 < NITER) issue_stage(smem, i + 3, t, bm, bn);
        cp_wait2();
        __syncthreads();   // stage i+1 ready; all reads of slot (i+3)%4 done

        if (i + 1 < NITER) {
            char* An = smem + SM_STAGE + ((i + 1) % NSTAGE) * STAGE_BYTES;
            LDFRAG(0, An, An + STAGE_A_BYTES, 0);   // next chunk kg0
        }
        MMA_ALL(1);                             // kg1
    }

    // Epilogue: bias -> per-activation affine -> activations -> attn mix
    const float*  sB  = (const float*)(smem + SM_B);
    const float4* sWF = (const float4*)(smem + SM_WF);
    const float4* sBF = (const float4*)(smem + SM_BF);
    const float4* sAT = (const float4*)(smem + SM_ATTN);
    const float inv_sqrt2 = 0.70710678118654752f;

#pragma unroll
    for (int mt = 0; mt < 4; mt++) {
#pragma unroll
        for (int half = 0; half < 2; half++) {
            int lr = m0 + mt * 16 + (lane >> 2) + half * 8;
            float4 at = sAT[lr];
            float* orow = out + (size_t)(bm + lr) * N_TOT + bn;
#pragma unroll
            for (int nt = 0; nt < 4; nt++) {
                int col0 = n0 + nt * 8 + (lane & 3) * 2;
                float2 res;
#pragma unroll
                for (int h = 0; h < 2; h++) {
                    int col = col0 + h;
                    float s = c[mt][nt][half * 2 + h] + sB[col];
                    float4 wfv = sWF[col];
                    float4 bfv = sBF[col];
                    float z0 = fmaf(s, wfv.x, bfv.x);
                    float z1 = fmaf(s, wfv.y, bfv.y);
                    float z2 = fmaf(s, wfv.z, bfv.z);
                    float z3 = fmaf(s, wfv.w, bfv.w);
                    float r0 = fmaxf(z0, 0.f);
                    float r1 = __fdividef(1.f, 1.f + __expf(-z1));
                    float r2 = 1.f - __fdividef(2.f, __expf(2.f * z2) + 1.f);
                    float r3 = 0.5f * z3 * (1.f + erff(z3 * inv_sqrt2));
                    float v = r0 * at.x + r1 * at.y + r2 * at.z + r3 * at.w;
                    if (h == 0) res.x = v; else res.y = v;
                }
                *(float2*)(orow + col0) = res;
            }
        }
    }
}

// ---------------------------------------------------------------------------
extern "C" void kernel_launch(void* const* d_in, const int* in_sizes, int n_in,
                              void* d_out, int out_size) {
    const float* x     = (const float*)d_in[0];
    const float* w     = (const float*)d_in[1];
    const float* b     = (const float*)d_in[2];
    const float* wf    = (const float*)d_in[3];
    const float* bf    = (const float*)d_in[4];
    const float* w_att = (const float*)d_in[5];
    const float* b_att = (const float*)d_in[6];
    float* out = (float*)d_out;

    cudaFuncSetAttribute(fused_gemm_hmma,
                         cudaFuncAttributeMaxDynamicSharedMemorySize, SM_TOTAL);

    prep_all<<<768, 256>>>(x, w, w_att, b_att);
    fused_gemm_hmma<<<dim3(N_TOT / BN, M_TOT / BM), 128, SM_TOTAL>>>(b, wf, bf, out);
}

// round 16
// speedup vs baseline: 1.2221x; 1.0447x over previous
#include <cuda_runtime.h>
#include <cuda_fp16.h>
#include <math.h>
#include <stdint.h>

// Shape (fixed): B=8, S=2048, D=1024, U=1024, A=4
#define M_TOT 16384
#define N_TOT 1024
#define K_TOT 1024

// GEMM tiling: fp16 mma.sync, 128 threads/CTA, CTA tile 128x64,
// warp tile 64x32 (2x2 warps), NSTAGE=4, 3 CTAs/SM
#define BM 128
#define BN 64
#define BKC 32            // fp16 K elems per stage chunk
#define NSTAGE 4
#define NITER 32          // 1024/32

// SMEM stage layout: padded rows for conflict-free ldmatrix
#define LDA 40            // A row stride in fp16 elems (80 B)
#define LDB 72            // B row stride in fp16 elems (144 B; 144%128=16)
#define STAGE_A_BYTES (BM * LDA * 2)      // 10240
#define STAGE_B_BYTES (BKC * LDB * 2)     // 4608
#define STAGE_BYTES   (STAGE_A_BYTES + STAGE_B_BYTES)   // 14848
#define SM_ATTN  0                         // 128 * float4 = 2048
#define SM_B     2048                      // 64 * float   = 256
#define SM_WF    2304                      // 64 * float4  = 1024
#define SM_BF    3328                      // 64 * float4  = 1024
#define SM_STAGE 4352
#define SM_TOTAL (SM_STAGE + NSTAGE * STAGE_BYTES)      // 63744 (3 CTAs/SM)

// ---------------- scratch (device globals; no allocation allowed) ----------
__device__ __half g_xh[(size_t)M_TOT * K_TOT];
__device__ __half g_wh[(size_t)K_TOT * N_TOT];   // w fp16, [K][N]
__device__ float g_attn[(size_t)M_TOT * 4];

// ---------------- helpers ---------------------------------------------------
__device__ __forceinline__ uint32_t smem_u32(const void* p) {
    return (uint32_t)__cvta_generic_to_shared(p);
}
__device__ __forceinline__ void cp16(uint32_t s, const void* g) {
    asm volatile("cp.async.cg.shared.global [%0], [%1], 16;" :: "r"(s), "l"(g));
}
__device__ __forceinline__ void cp_commit() {
    asm volatile("cp.async.commit_group;" ::: "memory");
}
__device__ __forceinline__ void cp_wait2() {
    asm volatile("cp.async.wait_group 2;" ::: "memory");
}
__device__ __forceinline__ void ldsm_x4(uint32_t* r, uint32_t a) {
    asm volatile("ldmatrix.sync.aligned.m8n8.x4.shared.b16 {%0,%1,%2,%3}, [%4];"
                 : "=r"(r[0]), "=r"(r[1]), "=r"(r[2]), "=r"(r[3]) : "r"(a));
}
__device__ __forceinline__ void ldsm_x4_t(uint32_t* r, uint32_t a) {
    asm volatile("ldmatrix.sync.aligned.m8n8.x4.trans.shared.b16 {%0,%1,%2,%3}, [%4];"
                 : "=r"(r[0]), "=r"(r[1]), "=r"(r[2]), "=r"(r[3]) : "r"(a));
}
__device__ __forceinline__ void mma_fp16(float* c, const uint32_t* a,
                                         uint32_t b0, uint32_t b1) {
    asm volatile(
        "mma.sync.aligned.m16n8k16.row.col.f32.f16.f16.f32 "
        "{%0,%1,%2,%3}, {%4,%5,%6,%7}, {%8,%9}, {%0,%1,%2,%3};"
        : "+f"(c[0]), "+f"(c[1]), "+f"(c[2]), "+f"(c[3])
        : "r"(a[0]), "r"(a[1]), "r"(a[2]), "r"(a[3]), "r"(b0), "r"(b1));
}

// ---------------------------------------------------------------------------
// Prep (merged): blocks [0, 512): attention softmax + x->fp16, 4 rows/warp,
// 2-deep register prefetch of x loads. Blocks [512, 768): w -> fp16.
// ---------------------------------------------------------------------------
__global__ __launch_bounds__(256) void prep_all(const float* __restrict__ x,
                                                const float* __restrict__ w,
                                                const float* __restrict__ w_att,
                                                const float* __restrict__ b_att) {
    if (blockIdx.x >= 512) {
        int base = (blockIdx.x - 512) * 1024 + threadIdx.x;
#pragma unroll
        for (int j = 0; j < 4; j++) {
            int i = base + j * 256;
            float4 v = ((const float4*)w)[i];
            unsigned short h0 = __half_as_ushort(__float2half_rn(v.x));
            unsigned short h1 = __half_as_ushort(__float2half_rn(v.y));
            unsigned short h2 = __half_as_ushort(__float2half_rn(v.z));
            unsigned short h3 = __half_as_ushort(__float2half_rn(v.w));
            ((uint2*)g_wh)[i] = make_uint2((uint32_t)h0 | ((uint32_t)h1 << 16),
                                           (uint32_t)h2 | ((uint32_t)h3 << 16));
        }
        return;
    }

    int warp = threadIdx.x >> 5;
    int lane = threadIdx.x & 31;
    int row0 = (blockIdx.x * 8 + warp) * 4;
    const float4* x4  = (const float4*)x;
    const float4* wa4 = (const float4*)w_att;

    float acc[4][4];
#pragma unroll
    for (int r = 0; r < 4; r++)
#pragma unroll
        for (int j = 0; j < 4; j++) acc[r][j] = 0.f;

    // Prefetch chunk 0's x loads
    float4 vbuf[4];
#pragma unroll
    for (int r = 0; r < 4; r++)
        vbuf[r] = x4[(size_t)(row0 + r) * 256 + lane];

#pragma unroll
    for (int i = 0; i < 8; i++) {
        int q = i * 32 + lane;
        float4 w0 = wa4[q * 4 + 0], w1 = wa4[q * 4 + 1];
        float4 w2 = wa4[q * 4 + 2], w3 = wa4[q * 4 + 3];
        float4 vcur[4];
#pragma unroll
        for (int r = 0; r < 4; r++) vcur[r] = vbuf[r];
        if (i < 7) {
#pragma unroll
            for (int r = 0; r < 4; r++)
                vbuf[r] = x4[(size_t)(row0 + r) * 256 + q + 32];
        }
#pragma unroll
        for (int r = 0; r < 4; r++) {
            float4 v = vcur[r];
            acc[r][0] = fmaf(v.x, w0.x, fmaf(v.y, w1.x,
                        fmaf(v.z, w2.x, fmaf(v.w, w3.x, acc[r][0]))));
            acc[r][1] = fmaf(v.x, w0.y, fmaf(v.y, w1.y,
                        fmaf(v.z, w2.y, fmaf(v.w, w3.y, acc[r][1]))));
            acc[r][2] = fmaf(v.x, w0.z, fmaf(v.y, w1.z,
                        fmaf(v.z, w2.z, fmaf(v.w, w3.z, acc[r][2]))));
            acc[r][3] = fmaf(v.x, w0.w, fmaf(v.y, w1.w,
                        fmaf(v.z, w2.w, fmaf(v.w, w3.w, acc[r][3]))));
            unsigned short h0 = __half_as_ushort(__float2half_rn(v.x));
            unsigned short h1 = __half_as_ushort(__float2half_rn(v.y));
            unsigned short h2 = __half_as_ushort(__float2half_rn(v.z));
            unsigned short h3 = __half_as_ushort(__float2half_rn(v.w));
            ((uint2*)g_xh)[(size_t)(row0 + r) * 256 + q] =
                make_uint2((uint32_t)h0 | ((uint32_t)h1 << 16),
                           (uint32_t)h2 | ((uint32_t)h3 << 16));
        }
    }
#pragma unroll
    for (int r = 0; r < 4; r++)
#pragma unroll
        for (int off = 16; off; off >>= 1) {
            acc[r][0] += __shfl_xor_sync(0xffffffffu, acc[r][0], off);
            acc[r][1] += __shfl_xor_sync(0xffffffffu, acc[r][1], off);
            acc[r][2] += __shfl_xor_sync(0xffffffffu, acc[r][2], off);
            acc[r][3] += __shfl_xor_sync(0xffffffffu, acc[r][3], off);
        }
    if (lane < 4) {
        float a0 = acc[lane][0] + b_att[0];
        float a1 = acc[lane][1] + b_att[1];
        float a2 = acc[lane][2] + b_att[2];
        float a3 = acc[lane][3] + b_att[3];
        float mx = fmaxf(fmaxf(a0, a1), fmaxf(a2, a3));
        float e0 = expf(a0 - mx), e1 = expf(a1 - mx);
        float e2 = expf(a2 - mx), e3 = expf(a3 - mx);
        float inv = 1.f / (e0 + e1 + e2 + e3);
        ((float4*)g_attn)[row0 + lane] =
            make_float4(e0 * inv, e1 * inv, e2 * inv, e3 * inv);
    }
}

// ---------------------------------------------------------------------------
// Main fused GEMM: fp16 mma.sync, warp tile 64x32, R9 mainloop schedule.
// 128 threads, 4 warps (2x2), 3 CTAs/SM. Epilogue mixture PINNED (fmaf chain).
// ---------------------------------------------------------------------------
__device__ __forceinline__ void issue_stage(char* smem, int idx, int t,
                                            int bm, int bn) {
    int kt = idx * BKC;
    char* A = smem + SM_STAGE + (idx % NSTAGE) * STAGE_BYTES;
    char* B = A + STAGE_A_BYTES;
#pragma unroll
    for (int i = 0; i < 4; i++) {
        int id  = t + i * 128;
        int row = id >> 2, cq = id & 3;
        cp16(smem_u32(A + row * (LDA * 2) + cq * 16),
             g_xh + (size_t)(bm + row) * K_TOT + kt + cq * 8);
    }
#pragma unroll
    for (int i = 0; i < 2; i++) {
        int id  = t + i * 128;
        int row = id >> 3, cq = id & 7;
        cp16(smem_u32(B + row * (LDB * 2) + cq * 16),
             g_wh + (size_t)(kt + row) * N_TOT + bn + cq * 8);
    }
    cp_commit();
}

__global__ __launch_bounds__(128, 3)
void fused_gemm_hmma(const float* __restrict__ b,
                     const float* __restrict__ wf,
                     const float* __restrict__ bf,
                     float* __restrict__ out) {
    extern __shared__ char smem[];
    const int t    = threadIdx.x;
    const int wid  = t >> 5;
    const int lane = t & 31;
    const int bm   = blockIdx.y * BM;
    const int bn   = blockIdx.x * BN;
    const int m0   = (wid >> 1) * 64;    // warp M offset
    const int n0   = (wid & 1) * 32;     // warp N offset

    // Stage epilogue tables (128 threads)
    ((float4*)(smem + SM_ATTN))[t] = ((const float4*)g_attn)[bm + t];
    if (t < 64) {
        ((float*)(smem + SM_B))[t]   = b[bn + t];
        ((float4*)(smem + SM_WF))[t] = ((const float4*)wf)[bn + t];
        ((float4*)(smem + SM_BF))[t] = ((const float4*)bf)[bn + t];
    }

    issue_stage(smem, 0, t, bm, bn);
    issue_stage(smem, 1, t, bm, bn);
    issue_stage(smem, 2, t, bm, bn);

    float c[4][4][4];
#pragma unroll
    for (int mt = 0; mt < 4; mt++)
#pragma unroll
        for (int nt = 0; nt < 4; nt++)
#pragma unroll
            for (int r = 0; r < 4; r++) c[mt][nt][r] = 0.f;

    const int lrow = lane & 15;
    const int lcol = (lane >> 4) * 8;

    // Fragment double buffers
    uint32_t af[2][4][4], bb[2][2][4];

#define LDFRAG(buf, Aptr, Bptr, k0)                                           \
    do {                                                                      \
        _Pragma("unroll")                                                     \
        for (int mt = 0; mt < 4; mt++)                                        \
            ldsm_x4(af[buf][mt], smem_u32((Aptr) +                            \
                    ((m0 + mt * 16 + lrow) * LDA + (k0) + lcol) * 2));        \
        _Pragma("unroll")                                                     \
        for (int ng = 0; ng < 2; ng++)                                        \
            ldsm_x4_t(bb[buf][ng], smem_u32((Bptr) +                          \
                    (((k0) + lrow) * LDB + n0 + ng * 16 + lcol) * 2));        \
    } while (0)

#define MMA_ALL(buf)                                                          \
    do {                                                                      \
        _Pragma("unroll")                                                     \
        for (int mt = 0; mt < 4; mt++)                                        \
            _Pragma("unroll")                                                 \
            for (int nt = 0; nt < 4; nt++)                                    \
                mma_fp16(c[mt][nt], af[buf][mt],                              \
                         bb[buf][nt >> 1][(nt & 1) * 2],                      \
                         bb[buf][nt >> 1][(nt & 1) * 2 + 1]);                 \
    } while (0)

    cp_wait2();        // stage 0 complete
    __syncthreads();
    {
        char* A0 = smem + SM_STAGE;
        LDFRAG(0, A0, A0 + STAGE_A_BYTES, 0);   // chunk 0, k-group 0
    }

    for (int i = 0; i < NITER; i++) {
        char* A = smem + SM_STAGE + (i % NSTAGE) * STAGE_BYTES;
        char* B = A + STAGE_A_BYTES;

        LDFRAG(1, A, B, 16);                    // kg1 of chunk i
        MMA_ALL(0);                             // kg0
        if (i + 3 < NITER) issue_stage(smem, i + 3, t, bm, bn);
        cp_wait2();
        __syncthreads();   // stage i+1 ready; all reads of slot (i+3)%4 done

        if (i + 1 < NITER) {
            char* An = smem + SM_STAGE + ((i + 1) % NSTAGE) * STAGE_BYTES;
            LDFRAG(0, An, An + STAGE_A_BYTES, 0);   // next chunk kg0
        }
        MMA_ALL(1);                             // kg1
    }

    // Epilogue: bias -> per-activation affine -> activations -> attn mix
    const float*  sB  = (const float*)(smem + SM_B);
    const float4* sWF = (const float4*)(smem + SM_WF);
    const float4* sBF = (const float4*)(smem + SM_BF);
    const float4* sAT = (const float4*)(smem + SM_ATTN);
    const float inv_sqrt2 = 0.70710678118654752f;

#pragma unroll
    for (int mt = 0; mt < 4; mt++) {
#pragma unroll
        for (int half = 0; half < 2; half++) {
            int lr = m0 + mt * 16 + (lane >> 2) + half * 8;
            float4 at = sAT[lr];
            float* orow = out + (size_t)(bm + lr) * N_TOT + bn;
#pragma unroll
            for (int nt = 0; nt < 4; nt++) {
                int col0 = n0 + nt * 8 + (lane & 3) * 2;
                float2 res;
#pragma unroll
                for (int h = 0; h < 2; h++) {
                    int col = col0 + h;
                    float s = c[mt][nt][half * 2 + h] + sB[col];
                    float4 wfv = sWF[col];
                    float4 bfv = sBF[col];
                    float z0 = fmaf(s, wfv.x, bfv.x);
                    float z1 = fmaf(s, wfv.y, bfv.y);
                    float z2 = fmaf(s, wfv.z, bfv.z);
                    float z3 = fmaf(s, wfv.w, bfv.w);
                    float r0 = fmaxf(z0, 0.f);
                    float r1 = __fdividef(1.f, 1.f + __expf(-z1));
                    float r2 = 1.f - __fdividef(2.f, __expf(2.f * z2) + 1.f);
                    float r3 = 0.5f * z3 * (1.f + erff(z3 * inv_sqrt2));
                    // PINNED rounding order (explicit fmaf chain):
                    float v = fmaf(r3, at.w,
                              fmaf(r2, at.z,
                              fmaf(r1, at.y, r0 * at.x)));
                    if (h == 0) res.x = v; else res.y = v;
                }
                *(float2*)(orow + col0) = res;
            }
        }
    }
}

// ---------------------------------------------------------------------------
extern "C" void kernel_launch(void* const* d_in, const int* in_sizes, int n_in,
                              void* d_out, int out_size) {
    const float* x     = (const float*)d_in[0];
    const float* w     = (const float*)d_in[1];
    const float* b     = (const float*)d_in[2];
    const float* wf    = (const float*)d_in[3];
    const float* bf    = (const float*)d_in[4];
    const float* w_att = (const float*)d_in[5];
    const float* b_att = (const float*)d_in[6];
    float* out = (float*)d_out;

    cudaFuncSetAttribute(fused_gemm_hmma,
                         cudaFuncAttributeMaxDynamicSharedMemorySize, SM_TOTAL);

    prep_all<<<768, 256>>>(x, w, w_att, b_att);
    fused_gemm_hmma<<<dim3(N_TOT / BN, M_TOT / BM), 128, SM_TOTAL>>>(b, wf, bf, out);
}